// round 7
// baseline (speedup 1.0000x reference)
#include <cuda_runtime.h>

#define BB 256
#define D_IN 2048
#define HID 2048
#define NSEG 10
#define D_CTX 1024
#define OUT_DIM 100
#define KWIN 102
#define NROWS_SEG (HID*NSEG)

// seg lists: 4 buckets of 256 cols, cap 48 each (stride 192/row)
#define SCAP 48
#define SEG_STRIDE (4*SCAP)
// ff lists: 2 buckets of 1024 cols, cap 104 each (stride 208/row)
#define FCAP 104
#define FF_STRIDE (2*FCAP)

struct __align__(8) Ent { float v; unsigned off; };

// ---- static scratch ----
__device__ Ent   g_segL[2][(size_t)NROWS_SEG*SEG_STRIDE];   // ~63 MB
__device__ int   g_segCnt[2][NROWS_SEG*4];
__device__ Ent   g_ffL[2][HID*FF_STRIDE];                   // ~6.8 MB
__device__ int   g_ffCnt[2][HID*2];
__device__ float g_ctxT[D_CTX*BB];                          // [c][b]
__device__ float g_xT[D_IN*BB];                             // [j][b]
__device__ float g_hT[HID*BB];                              // [u][b]
__device__ float g_yffT[HID*BB];
__device__ float g_yT[HID*BB];
__device__ Ent   g_win[BB*KWIN];

// ---------------- transpose: in [R=256][C] -> global [C][256] ----------------
__global__ void transpose_kernel(const float* __restrict__ in, int C, int which)
{
    __shared__ float t[32][33];
    float* out = which ? g_xT : g_ctxT;
    int c0 = blockIdx.x*32, r0 = blockIdx.y*32;
    int x = threadIdx.x, y0 = threadIdx.y;
    for (int yy = y0; yy < 32; yy += 8)
        t[yy][x] = in[(size_t)(r0+yy)*C + c0 + x];
    __syncthreads();
    for (int yy = y0; yy < 32; yy += 8)
        out[(size_t)(c0+yy)*BB + r0 + x] = t[x][yy];
}

// ---------------- seg extraction: bucketed by 256-col phase ----------------
__global__ void extract_seg_kernel(const float* __restrict__ w, const float* __restrict__ m, int layer)
{
    int row = blockIdx.x, tid = threadIdx.x;
    int lane = tid & 31, wrp = tid >> 5;
    const float4* w4 = (const float4*)(w + (size_t)row*D_CTX) + tid*2;
    const float4* m4 = (const float4*)(m + (size_t)row*D_CTX) + tid*2;
    float pv[8];
#pragma unroll
    for (int i = 0; i < 2; i++) {
        float4 a = w4[i], b = m4[i];
        pv[4*i+0] = a.x*b.x; pv[4*i+1] = a.y*b.y;
        pv[4*i+2] = a.z*b.z; pv[4*i+3] = a.w*b.w;
    }
    int cnt = 0;
#pragma unroll
    for (int j = 0; j < 8; j++) cnt += (pv[j] != 0.f);
    int inc = cnt;
#pragma unroll
    for (int d = 1; d < 32; d <<= 1) {
        int nv = __shfl_up_sync(0xFFFFFFFFu, inc, d);
        if (lane >= d) inc += nv;
    }
    int base = inc - cnt;
    Ent* out = g_segL[layer] + (size_t)row*SEG_STRIDE + wrp*SCAP;
    int pos = base;
#pragma unroll
    for (int j = 0; j < 8; j++) {
        if (pv[j] != 0.f) {
            if (pos < SCAP) {
                out[pos].v = pv[j];
                out[pos].off = (unsigned)((lane*8 + j) << 9);   // j_local * 512B (128-batch float row)
            }
            pos++;
        }
    }
    int tot = __shfl_sync(0xFFFFFFFFu, inc, 31);
    if (lane == 0) g_segCnt[layer][row*4 + wrp] = tot < SCAP ? tot : SCAP;
}

// ---------------- ff extraction: bucketed by 1024-col phase ----------------
__global__ void extract_ff_kernel(const float* __restrict__ w, const float* __restrict__ m, int layer)
{
    __shared__ int wsum[8];
    int row = blockIdx.x, tid = threadIdx.x;
    int lane = tid & 31, wrp = tid >> 5;      // 8 warps
    int bucket = tid >> 7;                    // warps 0-3 -> 0, 4-7 -> 1
    const float4* w4 = (const float4*)(w + (size_t)row*2048) + tid*2;
    const float4* m4 = (const float4*)(m + (size_t)row*2048) + tid*2;
    float pv[8];
#pragma unroll
    for (int i = 0; i < 2; i++) {
        float4 a = w4[i], b = m4[i];
        pv[4*i+0] = a.x*b.x; pv[4*i+1] = a.y*b.y;
        pv[4*i+2] = a.z*b.z; pv[4*i+3] = a.w*b.w;
    }
    int cnt = 0;
#pragma unroll
    for (int j = 0; j < 8; j++) cnt += (pv[j] != 0.f);
    int inc = cnt;
#pragma unroll
    for (int d = 1; d < 32; d <<= 1) {
        int nv = __shfl_up_sync(0xFFFFFFFFu, inc, d);
        if (lane >= d) inc += nv;
    }
    if (lane == 31) wsum[wrp] = inc;
    __syncthreads();
    int base = inc - cnt;
    for (int i = bucket*4; i < wrp; i++) base += wsum[i];
    Ent* out = g_ffL[layer] + (size_t)(row*2 + bucket)*FCAP;
    int pos = base;
    int jl0 = (tid & 127)*8;                  // col index local to bucket
#pragma unroll
    for (int j = 0; j < 8; j++) {
        if (pv[j] != 0.f) {
            if (pos < FCAP) {
                out[pos].v = pv[j];
                out[pos].off = (unsigned)((jl0 + j) << 7);   // j_local * 128B (32-batch float row)
            }
            pos++;
        }
    }
    if ((tid & 127) == 127) {
        int tot = wsum[bucket*4] + wsum[bucket*4+1] + wsum[bucket*4+2] + wsum[bucket*4+3];
        g_ffCnt[layer][row*2 + bucket] = tot < FCAP ? tot : FCAP;
    }
}

// ---------------- sparse feedforward (b-tile 32, 2 phases, staged + vectorized) ----------------
__global__ void __launch_bounds__(512,1) ff_kernel(int layer, const float* __restrict__ bias)
{
    extern __shared__ float sx[];                       // [1024][32] = 128KB
    Ent* stg = (Ent*)((char*)sx + 1024*32*4);           // 16 warps x 104 Ents (16B-aligned per warp)
    const float* inT = layer ? g_hT : g_xT;
    const Ent* lists = g_ffL[layer];
    const int* cnts  = g_ffCnt[layer];
    int tid = threadIdx.x, lane = tid & 31, wid = tid >> 5;
    int b0 = blockIdx.y*32, u0 = blockIdx.x*64;
    float acc[4] = {0.f,0.f,0.f,0.f};
    Ent* st = stg + wid*FCAP;
    const char* sb = (const char*)sx + lane*4;
    for (int ph = 0; ph < 2; ph++) {
        __syncthreads();
        for (int jj = wid; jj < 1024; jj += 16)
            sx[jj*32 + lane] = inT[(size_t)((ph<<10)+jj)*BB + b0 + lane];
        __syncthreads();
        // preload k=0 bucket into regs (zero-padded beyond n)
        int u = u0 + wid;
        int n = cnts[u*2 + ph];
        const Ent* lp = lists + (size_t)(u*2 + ph)*FCAP;
        Ent e0 = {0,0}, e1 = {0,0}, e2 = {0,0}, e3 = {0,0};
        if (lane      < n) e0 = lp[lane];
        if (lane + 32 < n) e1 = lp[lane+32];
        if (lane + 64 < n) e2 = lp[lane+64];
        if (lane <  8 && lane + 96 < n) e3 = lp[lane+96];
#pragma unroll
        for (int k = 0; k < 4; k++) {
            st[lane] = e0; st[lane+32] = e1; st[lane+64] = e2;
            if (lane < 8) st[lane+96] = e3;
            __syncwarp();
            int ncur = n;
            if (k < 3) {
                u = u0 + wid + (k+1)*16;
                n = cnts[u*2 + ph];
                lp = lists + (size_t)(u*2 + ph)*FCAP;
                e0 = {0,0}; e1 = {0,0}; e2 = {0,0}; e3 = {0,0};
                if (lane      < n) e0 = lp[lane];
                if (lane + 32 < n) e1 = lp[lane+32];
                if (lane + 64 < n) e2 = lp[lane+64];
                if (lane <  8 && lane + 96 < n) e3 = lp[lane+96];
            }
            // vectorized: 4 entries per iter via two uint4 pair-loads (padding contributes 0)
            int ng = (ncur + 3) >> 2;
            const uint4* stv = (const uint4*)st;
            float a0 = 0.f, a1 = 0.f;
            for (int g = 0; g < ng; g++) {
                uint4 q0 = stv[g*2], q1 = stv[g*2+1];
                a0 += *(const float*)(sb + q0.y) * __uint_as_float(q0.x);
                a1 += *(const float*)(sb + q0.w) * __uint_as_float(q0.z);
                a0 += *(const float*)(sb + q1.y) * __uint_as_float(q1.x);
                a1 += *(const float*)(sb + q1.w) * __uint_as_float(q1.z);
            }
            acc[k] += a0 + a1;
            __syncwarp();
        }
    }
#pragma unroll
    for (int k = 0; k < 4; k++) {
        int u = u0 + wid + k*16;
        g_yffT[(size_t)u*BB + b0 + lane] = acc[k] + bias[u];
    }
}

// ---------------- dendrite einsum + gate (b-tile 128 float4, staged + vectorized) ----------------
__global__ void __launch_bounds__(512,1) dend_kernel(int layer)
{
    extern __shared__ float tile[];                     // [256][128] = 128KB
    Ent* stg = (Ent*)((char*)tile + 256*128*4);         // 16 warps x 48 Ents (16B-aligned per warp)
    const int* cnts = g_segCnt[layer];
    int tid = threadIdx.x, lane = tid & 31, wid = tid >> 5;
    int u = blockIdx.x*16 + wid;
    int b0 = blockIdx.y*128;
    Ent* st = stg + wid*SCAP;
    const char* tb = (const char*)tile + lane*16;
    float4 dacc[NSEG];
#pragma unroll
    for (int s = 0; s < NSEG; s++) dacc[s] = make_float4(0.f,0.f,0.f,0.f);

    for (int p = 0; p < 4; p++) {
        __syncthreads();
        for (int idx = tid; idx < 256*32; idx += 512) {
            int r = idx >> 5, c = idx & 31;
            ((float4*)tile)[idx] = *(const float4*)&g_ctxT[(size_t)(256*p + r)*BB + b0 + c*4];
        }
        __syncthreads();
        // preload s=0 (zero-padded beyond n; all 48 slots written)
        int n = cnts[(u*NSEG + 0)*4 + p];
        const Ent* lp = g_segL[layer] + (size_t)(u*NSEG + 0)*SEG_STRIDE + p*SCAP;
        Ent c0 = {0,0}, c1 = {0,0};
        if (lane < n) c0 = lp[lane];
        if (lane < 16 && lane + 32 < n) c1 = lp[lane+32];
#pragma unroll
        for (int s = 0; s < NSEG; s++) {
            st[lane] = c0;
            if (lane < 16) st[lane+32] = c1;
            __syncwarp();
            int ncur = n;
            if (s < NSEG-1) {
                n = cnts[(u*NSEG + s+1)*4 + p];
                lp = g_segL[layer] + (size_t)(u*NSEG + s+1)*SEG_STRIDE + p*SCAP;
                c0 = {0,0}; c1 = {0,0};
                if (lane < n) c0 = lp[lane];
                if (lane < 16 && lane + 32 < n) c1 = lp[lane+32];
            }
            // vectorized: 4 entries per iter via two uint4 pair-loads (padding contributes 0)
            int ng = (ncur + 3) >> 2;
            const uint4* stv = (const uint4*)st;
            float4 a = dacc[s];
            for (int g = 0; g < ng; g++) {
                uint4 q0 = stv[g*2], q1 = stv[g*2+1];
                float v0 = __uint_as_float(q0.x), v1 = __uint_as_float(q0.z);
                float v2 = __uint_as_float(q1.x), v3 = __uint_as_float(q1.z);
                float4 cv0 = *(const float4*)(tb + q0.y);
                float4 cv1 = *(const float4*)(tb + q0.w);
                float4 cv2 = *(const float4*)(tb + q1.y);
                float4 cv3 = *(const float4*)(tb + q1.w);
                a.x += cv0.x*v0; a.y += cv0.y*v0; a.z += cv0.z*v0; a.w += cv0.w*v0;
                a.x += cv1.x*v1; a.y += cv1.y*v1; a.z += cv1.z*v1; a.w += cv1.w*v1;
                a.x += cv2.x*v2; a.y += cv2.y*v2; a.z += cv2.z*v2; a.w += cv2.w*v2;
                a.x += cv3.x*v3; a.y += cv3.y*v3; a.z += cv3.z*v3; a.w += cv3.w*v3;
            }
            dacc[s] = a;
            __syncwarp();
        }
    }
    // per-batch abs-argmax over segments (strict > = first-index tie rule)
    float4 best = make_float4(-1.f,-1.f,-1.f,-1.f);
    float4 ch   = make_float4(0.f,0.f,0.f,0.f);
#pragma unroll
    for (int s = 0; s < NSEG; s++) {
        float4 d = dacc[s];
        if (fabsf(d.x) > best.x) { best.x = fabsf(d.x); ch.x = d.x; }
        if (fabsf(d.y) > best.y) { best.y = fabsf(d.y); ch.y = d.y; }
        if (fabsf(d.z) > best.z) { best.z = fabsf(d.z); ch.z = d.z; }
        if (fabsf(d.w) > best.w) { best.w = fabsf(d.w); ch.w = d.w; }
    }
    float4 yf = *(const float4*)&g_yffT[(size_t)u*BB + b0 + lane*4];
    float4 o;
    o.x = yf.x / (1.f + __expf(-ch.x));
    o.y = yf.y / (1.f + __expf(-ch.y));
    o.z = yf.z / (1.f + __expf(-ch.z));
    o.w = yf.w / (1.f + __expf(-ch.w));
    *(float4*)&g_yT[(size_t)u*BB + b0 + lane*4] = o;
}

// ---------------- exact per-row top-K (radix select) ----------------
__global__ void kwin_kernel()
{
    __shared__ unsigned keys[HID];
    __shared__ float vals[HID];
    __shared__ int hist[256];
    __shared__ int s_digit, s_kk;
    __shared__ unsigned char keep[HID];
    int b = blockIdx.x, tid = threadIdx.x;   // 256 threads
    for (int r = 0; r < HID/256; r++) {
        int u = tid + r*256;
        float f = g_yT[(size_t)u*BB + b];
        vals[u] = f;
        unsigned x = __float_as_uint(f);
        keys[u] = (x & 0x80000000u) ? ~x : (x | 0x80000000u);
    }
    if (tid == 0) s_kk = KWIN;
    __syncthreads();
    unsigned pref = 0, pmask = 0;
    for (int pass = 0; pass < 4; pass++) {
        int shift = 24 - 8*pass;
        hist[tid] = 0;
        __syncthreads();
        for (int r = 0; r < HID/256; r++) {
            unsigned kk = keys[tid + r*256];
            if ((kk & pmask) == pref) atomicAdd(&hist[(kk >> shift) & 255], 1);
        }
        __syncthreads();
        if (tid == 0) {
            int kk = s_kk, d = 255;
            for (; d > 0; d--) { if (hist[d] >= kk) break; kk -= hist[d]; }
            s_digit = d; s_kk = kk;
        }
        __syncthreads();
        pref  |= ((unsigned)s_digit) << shift;
        pmask |= 0xFFu << shift;
    }
    unsigned kth = pref;
    int need_eq = s_kk;
    for (int r = 0; r < HID/256; r++) {
        int u = tid + r*256;
        unsigned kk = keys[u];
        bool kp = (kk > kth);
        if (kk == kth) {
            int cnt = 0;
            for (int j = 0; j < u; j++) if (keys[j] == kth) cnt++;
            kp = (cnt < need_eq);
        }
        keep[u] = kp;
        g_hT[(size_t)u*BB + b] = kp ? vals[u] : 0.f;
    }
    __syncthreads();
    if (tid < 32) {
        int base = 0;
        for (int ch = 0; ch < HID/32; ch++) {
            int u = ch*32 + tid;
            bool kp = keep[u] != 0;
            unsigned mm = __ballot_sync(0xFFFFFFFFu, kp);
            if (kp) {
                int pos = base + __popc(mm & ((1u << tid) - 1u));
                g_win[b*KWIN + pos].v = vals[u];
                g_win[b*KWIN + pos].off = (unsigned)u;
            }
            base += __popc(mm);
        }
    }
}

// ---------------- Dale output head on winner lists ----------------
__global__ void out_kernel(const float* __restrict__ Wex, const float* __restrict__ Wix,
                           const float* __restrict__ Wei, const float* __restrict__ bout,
                           float* __restrict__ out)
{
    __shared__ float sv[KWIN];
    __shared__ int   si[KWIN];
    __shared__ float red[128];
    int b = blockIdx.x, tid = threadIdx.x;   // 128 threads
    if (tid < KWIN) { Ent e = g_win[b*KWIN + tid]; sv[tid] = e.v; si[tid] = (int)e.off; }
    __syncthreads();
    float tpart = 0.f;
    for (int k = tid; k < KWIN; k += 128) tpart += sv[k]*Wix[si[k]];
    red[tid] = tpart;
    __syncthreads();
    for (int s = 64; s > 0; s >>= 1) { if (tid < s) red[tid] += red[tid+s]; __syncthreads(); }
    float t = red[0];
    if (tid < OUT_DIM) {
        float a = 0.f;
        const float* Wr = Wex + (size_t)tid*HID;
        for (int k = 0; k < KWIN; k++) a += sv[k]*Wr[si[k]];
        out[b*OUT_DIM + tid] = a - Wei[tid]*t + bout[tid];
    }
}

// ---------------- launch ----------------
extern "C" void kernel_launch(void* const* d_in, const int* in_sizes, int n_in,
                              void* d_out, int out_size)
{
    const float* x      = (const float*)d_in[0];
    const float* ctx    = (const float*)d_in[1];
    const float* W1     = (const float*)d_in[2];
    const float* b1     = (const float*)d_in[3];
    const float* segW1  = (const float*)d_in[4];
    const float* maskW1 = (const float*)d_in[5];
    const float* maskS1 = (const float*)d_in[6];
    const float* W2     = (const float*)d_in[7];
    const float* b2     = (const float*)d_in[8];
    const float* segW2  = (const float*)d_in[9];
    const float* maskW2 = (const float*)d_in[10];
    const float* maskS2 = (const float*)d_in[11];
    const float* Wex    = (const float*)d_in[12];
    const float* Wix    = (const float*)d_in[13];
    const float* Wei    = (const float*)d_in[14];
    const float* bout   = (const float*)d_in[15];
    float* out = (float*)d_out;

    const int FF_SMEM   = 1024*32*4 + 16*FCAP*8;   // 128K + 13.3K
    const int DEND_SMEM = 256*128*4 + 16*SCAP*8;   // 128K + 6K
    cudaFuncSetAttribute((const void*)ff_kernel,   cudaFuncAttributeMaxDynamicSharedMemorySize, FF_SMEM);
    cudaFuncSetAttribute((const void*)dend_kernel, cudaFuncAttributeMaxDynamicSharedMemorySize, DEND_SMEM);

    dim3 tb(32, 8);
    transpose_kernel<<<dim3(D_CTX/32, BB/32), tb>>>(ctx, D_CTX, 0);
    transpose_kernel<<<dim3(D_IN/32,  BB/32), tb>>>(x,   D_IN,  1);

    extract_seg_kernel<<<NROWS_SEG, 128>>>(segW1, maskS1, 0);
    extract_seg_kernel<<<NROWS_SEG, 128>>>(segW2, maskS2, 1);
    extract_ff_kernel <<<HID,       256>>>(W1, maskW1, 0);
    extract_ff_kernel <<<HID,       256>>>(W2, maskW2, 1);

    dim3 ffg(HID/64, BB/32);     // (32, 8)
    dim3 ddg(HID/16, BB/128);    // (128, 2)

    ff_kernel  <<<ffg, 512, FF_SMEM>>>(0, b1);
    dend_kernel<<<ddg, 512, DEND_SMEM>>>(0);
    kwin_kernel<<<BB, 256>>>();

    ff_kernel  <<<ffg, 512, FF_SMEM>>>(1, b2);
    dend_kernel<<<ddg, 512, DEND_SMEM>>>(1);
    kwin_kernel<<<BB, 256>>>();

    out_kernel<<<BB, 128>>>(Wex, Wix, Wei, bout, out);
}

// round 13
// speedup vs baseline: 1.0693x; 1.0693x over previous
#include <cuda_runtime.h>

#define BB 256
#define D_IN 2048
#define HID 2048
#define NSEG 10
#define D_CTX 1024
#define OUT_DIM 100
#define KWIN 102
#define NROWS_SEG (HID*NSEG)

// seg lists: 4 buckets of 256 cols, cap 48 each (stride 192/row)
#define SCAP 48
#define SEG_STRIDE (4*SCAP)
// ff lists: 2 buckets of 1024 cols, cap 104 each (stride 208/row)
#define FCAP 104
#define FF_STRIDE (2*FCAP)

struct __align__(8) Ent { float v; unsigned off; };

// ---- static scratch ----
__device__ Ent   g_segL[2][(size_t)NROWS_SEG*SEG_STRIDE];   // ~63 MB
__device__ int   g_segCnt[2][NROWS_SEG*4];                  // [p][u][s] layout
__device__ Ent   g_ffL[2][HID*FF_STRIDE];                   // ~6.8 MB
__device__ int   g_ffCnt[2][HID*2];
__device__ float g_ctxT[D_CTX*BB];                          // [c][b]
__device__ float g_xT[D_IN*BB];                             // [j][b]
__device__ float g_hT[HID*BB];                              // [u][b]
__device__ float g_yffT[HID*BB];
__device__ float g_yT[HID*BB];
__device__ Ent   g_win[BB*KWIN];

// ---------------- transpose: in [R=256][C] -> global [C][256] ----------------
__global__ void transpose_kernel(const float* __restrict__ in, int C, int which)
{
    __shared__ float t[32][33];
    float* out = which ? g_xT : g_ctxT;
    int c0 = blockIdx.x*32, r0 = blockIdx.y*32;
    int x = threadIdx.x, y0 = threadIdx.y;
    for (int yy = y0; yy < 32; yy += 8)
        t[yy][x] = in[(size_t)(r0+yy)*C + c0 + x];
    __syncthreads();
    for (int yy = y0; yy < 32; yy += 8)
        out[(size_t)(c0+yy)*BB + r0 + x] = t[x][yy];
}

// ---------------- seg extraction: bucketed by 256-col phase ----------------
// 128 thr/row; warp w = bucket w (cols [256w,256w+256)); thread owns 8 cols.
// row = u*NSEG + s; counts written in [p][row] layout for coalesced dend reads.
__global__ void extract_seg_kernel(const float* __restrict__ w, const float* __restrict__ m, int layer)
{
    int row = blockIdx.x, tid = threadIdx.x;
    int lane = tid & 31, wrp = tid >> 5;
    const float4* w4 = (const float4*)(w + (size_t)row*D_CTX) + tid*2;
    const float4* m4 = (const float4*)(m + (size_t)row*D_CTX) + tid*2;
    float pv[8];
#pragma unroll
    for (int i = 0; i < 2; i++) {
        float4 a = w4[i], b = m4[i];
        pv[4*i+0] = a.x*b.x; pv[4*i+1] = a.y*b.y;
        pv[4*i+2] = a.z*b.z; pv[4*i+3] = a.w*b.w;
    }
    int cnt = 0;
#pragma unroll
    for (int j = 0; j < 8; j++) cnt += (pv[j] != 0.f);
    int inc = cnt;
#pragma unroll
    for (int d = 1; d < 32; d <<= 1) {
        int nv = __shfl_up_sync(0xFFFFFFFFu, inc, d);
        if (lane >= d) inc += nv;
    }
    int base = inc - cnt;
    Ent* out = g_segL[layer] + (size_t)row*SEG_STRIDE + wrp*SCAP;
    int pos = base;
#pragma unroll
    for (int j = 0; j < 8; j++) {
        if (pv[j] != 0.f) {
            if (pos < SCAP) {
                out[pos].v = pv[j];
                out[pos].off = (unsigned)((lane*8 + j) << 9);   // j_local * 512B (128-batch float row)
            }
            pos++;
        }
    }
    int tot = __shfl_sync(0xFFFFFFFFu, inc, 31);
    if (lane == 0) g_segCnt[layer][wrp*NROWS_SEG + row] = tot < SCAP ? tot : SCAP;
}

// ---------------- ff extraction: bucketed by 1024-col phase ----------------
__global__ void extract_ff_kernel(const float* __restrict__ w, const float* __restrict__ m, int layer)
{
    __shared__ int wsum[8];
    int row = blockIdx.x, tid = threadIdx.x;
    int lane = tid & 31, wrp = tid >> 5;      // 8 warps
    int bucket = tid >> 7;                    // warps 0-3 -> 0, 4-7 -> 1
    const float4* w4 = (const float4*)(w + (size_t)row*2048) + tid*2;
    const float4* m4 = (const float4*)(m + (size_t)row*2048) + tid*2;
    float pv[8];
#pragma unroll
    for (int i = 0; i < 2; i++) {
        float4 a = w4[i], b = m4[i];
        pv[4*i+0] = a.x*b.x; pv[4*i+1] = a.y*b.y;
        pv[4*i+2] = a.z*b.z; pv[4*i+3] = a.w*b.w;
    }
    int cnt = 0;
#pragma unroll
    for (int j = 0; j < 8; j++) cnt += (pv[j] != 0.f);
    int inc = cnt;
#pragma unroll
    for (int d = 1; d < 32; d <<= 1) {
        int nv = __shfl_up_sync(0xFFFFFFFFu, inc, d);
        if (lane >= d) inc += nv;
    }
    if (lane == 31) wsum[wrp] = inc;
    __syncthreads();
    int base = inc - cnt;
    for (int i = bucket*4; i < wrp; i++) base += wsum[i];
    Ent* out = g_ffL[layer] + (size_t)(row*2 + bucket)*FCAP;
    int pos = base;
    int jl0 = (tid & 127)*8;                  // col index local to bucket
#pragma unroll
    for (int j = 0; j < 8; j++) {
        if (pv[j] != 0.f) {
            if (pos < FCAP) {
                out[pos].v = pv[j];
                out[pos].off = (unsigned)((jl0 + j) << 7);   // j_local * 128B (32-batch float row)
            }
            pos++;
        }
    }
    if ((tid & 127) == 127) {
        int tot = wsum[bucket*4] + wsum[bucket*4+1] + wsum[bucket*4+2] + wsum[bucket*4+3];
        g_ffCnt[layer][row*2 + bucket] = tot < FCAP ? tot : FCAP;
    }
}

// ---------------- sparse feedforward: all 4 buckets preloaded before tile fill ----------------
__global__ void __launch_bounds__(512,1) ff_kernel(int layer, const float* __restrict__ bias)
{
    extern __shared__ float sx[];                       // [1024][32] = 128KB
    Ent* stg = (Ent*)((char*)sx + 1024*32*4);           // 16 warps x 2 x FCAP (double-buffered)
    const float* inT = layer ? g_hT : g_xT;
    const Ent* lists = g_ffL[layer];
    const int* cnts  = g_ffCnt[layer];
    int tid = threadIdx.x, lane = tid & 31, wid = tid >> 5;
    int b0 = blockIdx.y*32, u0 = blockIdx.x*64;
    float acc[4] = {0.f,0.f,0.f,0.f};
    Ent* stw = stg + wid*(2*FCAP);
    const char* sb = (const char*)sx + lane*4;
    for (int ph = 0; ph < 2; ph++) {
        // preload ALL 4 buckets of this phase into regs (covered by tile fill below)
        Ent ea[4], eb[4], ec[4], ed[4]; int nk[4];
#pragma unroll
        for (int k = 0; k < 4; k++) {
            int uu = u0 + wid + k*16;
            nk[k] = cnts[uu*2 + ph];
            const Ent* lp = lists + (size_t)(uu*2 + ph)*FCAP;
            ea[k].v=0.f; ea[k].off=0u; eb[k]=ea[k]; ec[k]=ea[k]; ed[k]=ea[k];
            if (lane      < nk[k]) ea[k] = lp[lane];
            if (lane + 32 < nk[k]) eb[k] = lp[lane+32];
            if (lane + 64 < nk[k]) ec[k] = lp[lane+64];
            if (lane <  8 && lane + 96 < nk[k]) ed[k] = lp[lane+96];
        }
        __syncthreads();   // previous phase compute done; tile reusable
        for (int jj = wid; jj < 1024; jj += 16)
            sx[jj*32 + lane] = inT[(size_t)((ph<<10)+jj)*BB + b0 + lane];
        // stage k=0 into buffer 0
        stw[lane] = ea[0]; stw[lane+32] = eb[0]; stw[lane+64] = ec[0];
        if (lane < 8) stw[lane+96] = ed[0];
        __syncthreads();
#pragma unroll
        for (int k = 0; k < 4; k++) {
            const uint4* stv = (const uint4*)(stw + (k&1)*FCAP);
            int ng = (nk[k] + 3) >> 2;
            float a0 = 0.f, a1 = 0.f;
            for (int g = 0; g < ng; g++) {
                uint4 q0 = stv[g*2], q1 = stv[g*2+1];
                a0 += *(const float*)(sb + q0.y) * __uint_as_float(q0.x);
                a1 += *(const float*)(sb + q0.w) * __uint_as_float(q0.z);
                a0 += *(const float*)(sb + q1.y) * __uint_as_float(q1.x);
                a1 += *(const float*)(sb + q1.w) * __uint_as_float(q1.z);
            }
            acc[k] += a0 + a1;
            if (k < 3) {   // stage next bucket into alternate buffer
                Ent* st1 = stw + ((k+1)&1)*FCAP;
                st1[lane] = ea[k+1]; st1[lane+32] = eb[k+1]; st1[lane+64] = ec[k+1];
                if (lane < 8) st1[lane+96] = ed[k+1];
            }
            __syncwarp();
        }
    }
#pragma unroll
    for (int k = 0; k < 4; k++) {
        int u = u0 + wid + k*16;
        g_yffT[(size_t)u*BB + b0 + lane] = acc[k] + bias[u];
    }
}

// ---------------- dendrite einsum + gate: depth-3 prefetch, double-buffered staging ----------------
__global__ void __launch_bounds__(512,1) dend_kernel(int layer)
{
    extern __shared__ float tile[];                     // [256][128] = 128KB
    Ent* stg = (Ent*)((char*)tile + 256*128*4);         // 16 warps x 2 x SCAP
    int tid = threadIdx.x, lane = tid & 31, wid = tid >> 5;
    int u = blockIdx.x*16 + wid;
    int b0 = blockIdx.y*128;
    Ent* stw = stg + wid*(2*SCAP);
    const char* tb = (const char*)tile + lane*16;
    const Ent* ubase = g_segL[layer] + (size_t)(u*NSEG)*SEG_STRIDE;
    const int* cnts = g_segCnt[layer];
    float4 dacc[NSEG];
#pragma unroll
    for (int s = 0; s < NSEG; s++) dacc[s] = make_float4(0.f,0.f,0.f,0.f);

    for (int p = 0; p < 4; p++) {
        const Ent* base = ubase + p*SCAP;
        int myCnt = 0;
        if (lane < NSEG) myCnt = cnts[p*NROWS_SEG + u*NSEG + lane];
        // depth-3 register prefetch of buckets s=0,1,2 (covered by tile fill)
        Ent ra[3], rb[3];
#pragma unroll
        for (int i = 0; i < 3; i++) {
            int ni = __shfl_sync(0xFFFFFFFFu, myCnt, i);
            const Ent* lp = base + (size_t)i*SEG_STRIDE;
            ra[i].v=0.f; ra[i].off=0u; rb[i]=ra[i];
            if (lane < ni) ra[i] = lp[lane];
            if (lane < 16 && lane + 32 < ni) rb[i] = lp[lane+32];
        }
        __syncthreads();   // previous phase compute done
        for (int idx = tid; idx < 256*32; idx += 512) {
            int r = idx >> 5, c = idx & 31;
            ((float4*)tile)[idx] = *(const float4*)&g_ctxT[(size_t)(256*p + r)*BB + b0 + c*4];
        }
        // stage s=0 into buffer 0
        stw[lane] = ra[0]; if (lane < 16) stw[lane+32] = rb[0];
        __syncthreads();
#pragma unroll
        for (int s = 0; s < NSEG; s++) {
            int ncur = __shfl_sync(0xFFFFFFFFu, myCnt, s);
            // issue prefetch for s+3 into the reg set freed last iteration
            if (s + 3 < NSEG) {
                int nn = __shfl_sync(0xFFFFFFFFu, myCnt, s+3);
                const Ent* lp = base + (size_t)(s+3)*SEG_STRIDE;
                ra[s%3].v=0.f; ra[s%3].off=0u; rb[s%3]=ra[s%3];
                if (lane < nn) ra[s%3] = lp[lane];
                if (lane < 16 && lane + 32 < nn) rb[s%3] = lp[lane+32];
            }
            // compute segment s from buffer s&1
            const uint4* stv = (const uint4*)(stw + (s&1)*SCAP);
            int ng = (ncur + 3) >> 2;
            float4 a = dacc[s];
            for (int g = 0; g < ng; g++) {
                uint4 q0 = stv[g*2], q1 = stv[g*2+1];
                float v0 = __uint_as_float(q0.x), v1 = __uint_as_float(q0.z);
                float v2 = __uint_as_float(q1.x), v3 = __uint_as_float(q1.z);
                float4 cv0 = *(const float4*)(tb + q0.y);
                float4 cv1 = *(const float4*)(tb + q0.w);
                float4 cv2 = *(const float4*)(tb + q1.y);
                float4 cv3 = *(const float4*)(tb + q1.w);
                a.x += cv0.x*v0; a.y += cv0.y*v0; a.z += cv0.z*v0; a.w += cv0.w*v0;
                a.x += cv1.x*v1; a.y += cv1.y*v1; a.z += cv1.z*v1; a.w += cv1.w*v1;
                a.x += cv2.x*v2; a.y += cv2.y*v2; a.z += cv2.z*v2; a.w += cv2.w*v2;
                a.x += cv3.x*v3; a.y += cv3.y*v3; a.z += cv3.z*v3; a.w += cv3.w*v3;
            }
            dacc[s] = a;
            // stage s+1 into alternate buffer (regs loaded 2 segments ago)
            if (s + 1 < NSEG) {
                Ent* st1 = stw + ((s+1)&1)*SCAP;
                st1[lane] = ra[(s+1)%3];
                if (lane < 16) st1[lane+32] = rb[(s+1)%3];
            }
            __syncwarp();
        }
    }
    // per-batch abs-argmax over segments (strict > = first-index tie rule)
    float4 best = make_float4(-1.f,-1.f,-1.f,-1.f);
    float4 ch   = make_float4(0.f,0.f,0.f,0.f);
#pragma unroll
    for (int s = 0; s < NSEG; s++) {
        float4 d = dacc[s];
        if (fabsf(d.x) > best.x) { best.x = fabsf(d.x); ch.x = d.x; }
        if (fabsf(d.y) > best.y) { best.y = fabsf(d.y); ch.y = d.y; }
        if (fabsf(d.z) > best.z) { best.z = fabsf(d.z); ch.z = d.z; }
        if (fabsf(d.w) > best.w) { best.w = fabsf(d.w); ch.w = d.w; }
    }
    float4 yf = *(const float4*)&g_yffT[(size_t)u*BB + b0 + lane*4];
    float4 o;
    o.x = yf.x / (1.f + __expf(-ch.x));
    o.y = yf.y / (1.f + __expf(-ch.y));
    o.z = yf.z / (1.f + __expf(-ch.z));
    o.w = yf.w / (1.f + __expf(-ch.w));
    *(float4*)&g_yT[(size_t)u*BB + b0 + lane*4] = o;
}

// ---------------- exact per-row top-K (radix select, parallel tie-rank) ----------------
__global__ void kwin_kernel()
{
    __shared__ unsigned keys[HID];
    __shared__ float vals[HID];
    __shared__ int hist[256];
    __shared__ int s_digit, s_kk;
    __shared__ int eqw[8];
    __shared__ unsigned char keep[HID];
    int b = blockIdx.x, tid = threadIdx.x;   // 256 threads
    int lane = tid & 31, wrp = tid >> 5;
    for (int r = 0; r < HID/256; r++) {
        int u = tid + r*256;
        float f = g_yT[(size_t)u*BB + b];
        vals[u] = f;
        unsigned x = __float_as_uint(f);
        keys[u] = (x & 0x80000000u) ? ~x : (x | 0x80000000u);
    }
    if (tid == 0) s_kk = KWIN;
    __syncthreads();
    unsigned pref = 0, pmask = 0;
    for (int pass = 0; pass < 4; pass++) {
        int shift = 24 - 8*pass;
        hist[tid] = 0;
        __syncthreads();
        for (int r = 0; r < HID/256; r++) {
            unsigned kk = keys[tid + r*256];
            if ((kk & pmask) == pref) atomicAdd(&hist[(kk >> shift) & 255], 1);
        }
        __syncthreads();
        if (tid == 0) {
            int kk = s_kk, d = 255;
            for (; d > 0; d--) { if (hist[d] >= kk) break; kk -= hist[d]; }
            s_digit = d; s_kk = kk;
        }
        __syncthreads();
        pref  |= ((unsigned)s_digit) << shift;
        pmask |= 0xFFu << shift;
    }
    unsigned kth = pref;
    int need_eq = s_kk;   // keep this many of the ==kth elements, lowest index first
    int runningEq = 0;
    for (int r = 0; r < HID/256; r++) {
        int u = r*256 + tid;
        unsigned kk = keys[u];
        bool eq = (kk == kth);
        unsigned bal = __ballot_sync(0xFFFFFFFFu, eq);
        if (lane == 0) eqw[wrp] = __popc(bal);
        __syncthreads();
        int off = runningEq;
        for (int wt = 0; wt < wrp; wt++) off += eqw[wt];
        int rank = off + __popc(bal & ((1u << lane) - 1u));
        bool kp = (kk > kth) || (eq && rank < need_eq);
        keep[u] = kp;
        g_hT[(size_t)u*BB + b] = kp ? vals[u] : 0.f;
        int tot = 0;
        for (int wt = 0; wt < 8; wt++) tot += eqw[wt];
        runningEq += tot;
        __syncthreads();
    }
    if (tid < 32) {   // deterministic index-ordered winner list
        int base = 0;
        for (int ch = 0; ch < HID/32; ch++) {
            int u = ch*32 + tid;
            bool kp = keep[u] != 0;
            unsigned mm = __ballot_sync(0xFFFFFFFFu, kp);
            if (kp) {
                int pos = base + __popc(mm & ((1u << tid) - 1u));
                g_win[b*KWIN + pos].v = vals[u];
                g_win[b*KWIN + pos].off = (unsigned)u;
            }
            base += __popc(mm);
        }
    }
}

// ---------------- Dale output head on winner lists ----------------
__global__ void out_kernel(const float* __restrict__ Wex, const float* __restrict__ Wix,
                           const float* __restrict__ Wei, const float* __restrict__ bout,
                           float* __restrict__ out)
{
    __shared__ float sv[KWIN];
    __shared__ int   si[KWIN];
    __shared__ float red[128];
    int b = blockIdx.x, tid = threadIdx.x;   // 128 threads
    if (tid < KWIN) { Ent e = g_win[b*KWIN + tid]; sv[tid] = e.v; si[tid] = (int)e.off; }
    __syncthreads();
    float tpart = 0.f;
    for (int k = tid; k < KWIN; k += 128) tpart += sv[k]*Wix[si[k]];
    red[tid] = tpart;
    __syncthreads();
    for (int s = 64; s > 0; s >>= 1) { if (tid < s) red[tid] += red[tid+s]; __syncthreads(); }
    float t = red[0];
    if (tid < OUT_DIM) {
        float a = 0.f;
        const float* Wr = Wex + (size_t)tid*HID;
        for (int k = 0; k < KWIN; k++) a += sv[k]*Wr[si[k]];
        out[b*OUT_DIM + tid] = a - Wei[tid]*t + bout[tid];
    }
}

// ---------------- launch ----------------
extern "C" void kernel_launch(void* const* d_in, const int* in_sizes, int n_in,
                              void* d_out, int out_size)
{
    const float* x      = (const float*)d_in[0];
    const float* ctx    = (const float*)d_in[1];
    const float* W1     = (const float*)d_in[2];
    const float* b1     = (const float*)d_in[3];
    const float* segW1  = (const float*)d_in[4];
    const float* maskW1 = (const float*)d_in[5];
    const float* maskS1 = (const float*)d_in[6];
    const float* W2     = (const float*)d_in[7];
    const float* b2     = (const float*)d_in[8];
    const float* segW2  = (const float*)d_in[9];
    const float* maskW2 = (const float*)d_in[10];
    const float* maskS2 = (const float*)d_in[11];
    const float* Wex    = (const float*)d_in[12];
    const float* Wix    = (const float*)d_in[13];
    const float* Wei    = (const float*)d_in[14];
    const float* bout   = (const float*)d_in[15];
    float* out = (float*)d_out;

    const int FF_SMEM   = 1024*32*4 + 16*2*FCAP*8;   // 128K + 26K
    const int DEND_SMEM = 256*128*4 + 16*2*SCAP*8;   // 128K + 12K
    cudaFuncSetAttribute((const void*)ff_kernel,   cudaFuncAttributeMaxDynamicSharedMemorySize, FF_SMEM);
    cudaFuncSetAttribute((const void*)dend_kernel, cudaFuncAttributeMaxDynamicSharedMemorySize, DEND_SMEM);

    dim3 tb(32, 8);
    transpose_kernel<<<dim3(D_CTX/32, BB/32), tb>>>(ctx, D_CTX, 0);
    transpose_kernel<<<dim3(D_IN/32,  BB/32), tb>>>(x,   D_IN,  1);

    extract_seg_kernel<<<NROWS_SEG, 128>>>(segW1, maskS1, 0);
    extract_seg_kernel<<<NROWS_SEG, 128>>>(segW2, maskS2, 1);
    extract_ff_kernel <<<HID,       256>>>(W1, maskW1, 0);
    extract_ff_kernel <<<HID,       256>>>(W2, maskW2, 1);

    dim3 ffg(HID/64, BB/32);     // (32, 8)
    dim3 ddg(HID/16, BB/128);    // (128, 2)

    ff_kernel  <<<ffg, 512, FF_SMEM>>>(0, b1);
    dend_kernel<<<ddg, 512, DEND_SMEM>>>(0);
    kwin_kernel<<<BB, 256>>>();

    ff_kernel  <<<ffg, 512, FF_SMEM>>>(1, b2);
    dend_kernel<<<ddg, 512, DEND_SMEM>>>(1);
    kwin_kernel<<<BB, 256>>>();

    out_kernel<<<BB, 128>>>(Wex, Wix, Wei, bout, out);
}